// round 6
// baseline (speedup 1.0000x reference)
#include <cuda_runtime.h>
#include <cuda_bf16.h>
#include <cstdint>

// GaussianKernel: N=32, R=128, F=128
// Gram form: D[i,j] = ||u_i||^2 - 2 u_i.v_j + ||v_j||^2,  u = x1 - mean, v = x2
// out = softmax_j( exp( exp(-D/(2 sigma^2)) ) )
//
// 128 blocks (1/SM), 512 threads = 16 warps.
// Split-F: warps 0-7 handle f in [0,64), warps 8-15 f in [64,128).
// Warp p(=w&7) owns i-rows 4p..4p+3; lane owns j = lane + 32q, q<4 (4i x 4j tile).
// Partial dots combined through smem; each warp epilogues 2 rows (balanced).

#define N_B 32
#define R_DIM 128
#define F_DIM 128
#define TIB 32
#define SSTR 132        // padded row stride (floats): conflict-free LDS.128

__device__ __forceinline__ unsigned long long f32x2_fma(unsigned long long a, unsigned long long b, unsigned long long c) {
    unsigned long long r;
    asm("fma.rn.f32x2 %0, %1, %2, %3;" : "=l"(r) : "l"(a), "l"(b), "l"(c));
    return r;
}
__device__ __forceinline__ void f32x2_unpack(unsigned long long u, float& lo, float& hi) {
    asm("mov.b64 {%0, %1}, %2;" : "=f"(lo), "=f"(hi) : "l"(u));
}

__global__ void __launch_bounds__(512, 1)
gaussian_gram_splitf(const float4* __restrict__ x1,
                     const float4* __restrict__ x2,
                     const float* __restrict__ sigma,
                     const float* __restrict__ mean,
                     float* __restrict__ out) {
    extern __shared__ float smem[];
    float* x2s   = smem;                          // [128][132]  v
    float* x1s   = x2s + R_DIM * SSTR;            // [32][132]   u = x1 - mean
    float* pd    = x1s + TIB * SSTR;              // [32][128]   partial dots
    float* normu = pd + TIB * R_DIM;              // [32]
    float* normv = normu + TIB;                   // [128]

    const int n    = blockIdx.y;
    const int i0   = blockIdx.x * TIB;
    const int t    = threadIdx.x;
    const int lane = t & 31;
    const int w    = t >> 5;                      // 0..15
    const int p    = w & 7;                       // i-row group: rows 4p..4p+3
    const int g    = w >> 3;                      // f-half

    const float mn = mean[0];
    const float sg = sigma[0];
    const float inv2s2 = 1.0f / (2.0f * sg * sg);

    // ---- fill v = x2[n] (coalesced float4, padded rows) ----
    const float4* x2g = x2 + (size_t)n * (R_DIM * F_DIM / 4);
    #pragma unroll
    for (int it = 0; it < (R_DIM * F_DIM / 4) / 512; ++it) {
        int idx4 = t + 512 * it;                  // 0..4095
        int row  = idx4 >> 5;
        int c4   = idx4 & 31;
        *(float4*)&x2s[row * SSTR + c4 * 4] = x2g[idx4];
    }
    // ---- fill u = x1 tile - mean (padded rows) ----
    const float4* x1g = x1 + ((size_t)n * R_DIM + i0) * (F_DIM / 4);
    #pragma unroll
    for (int it = 0; it < (TIB * F_DIM / 4) / 512; ++it) {
        int idx4 = t + 512 * it;                  // 0..1023
        int row  = idx4 >> 5;
        int c4   = idx4 & 31;
        float4 v = x1g[idx4];
        *(float4*)&x1s[row * SSTR + c4 * 4] = make_float4(v.x - mn, v.y - mn, v.z - mn, v.w - mn);
    }
    __syncthreads();

    // ---- norms (serial per row, conflict-free via 132 stride) ----
    if (t < 128) {                                // normv: row t
        const ulonglong2* vp = (const ulonglong2*)&x2s[t * SSTR];
        unsigned long long a0 = 0ull, a1 = 0ull;
        #pragma unroll
        for (int q = 0; q < 16; ++q) {
            ulonglong2 vv = vp[q];
            a0 = f32x2_fma(vv.x, vv.x, a0);
            a1 = f32x2_fma(vv.y, vv.y, a1);
        }
        float l0, h0, l1, h1;
        f32x2_unpack(a0, l0, h0); f32x2_unpack(a1, l1, h1);
        normv[t] = (l0 + h0) + (l1 + h1);
    } else if (t < 160) {                         // normu: row t-128
        int r = t - 128;
        const ulonglong2* up = (const ulonglong2*)&x1s[r * SSTR];
        unsigned long long a0 = 0ull, a1 = 0ull;
        #pragma unroll
        for (int q = 0; q < 16; ++q) {
            ulonglong2 uu = up[q];
            a0 = f32x2_fma(uu.x, uu.x, a0);
            a1 = f32x2_fma(uu.y, uu.y, a1);
        }
        float l0, h0, l1, h1;
        f32x2_unpack(a0, l0, h0); f32x2_unpack(a1, l1, h1);
        normu[r] = (l0 + h0) + (l1 + h1);
    }

    // ---- main loop: 4i x 4j tile over this warp's f-half ----
    unsigned long long acc[4][4];
    #pragma unroll
    for (int r = 0; r < 4; ++r)
        #pragma unroll
        for (int q = 0; q < 4; ++q) acc[r][q] = 0ull;

    const ulonglong2* brow = (const ulonglong2*)&x2s[lane * SSTR];
    const float* arow = &x1s[p * 4 * SSTR];
    const int bq_stride = 32 * SSTR / 4;          // ull2 units per 32 rows
    const int f4base = g * 16;

    #pragma unroll 4
    for (int ff = 0; ff < 16; ++ff) {
        const int f4 = f4base + ff;
        ulonglong2 b[4];
        #pragma unroll
        for (int q = 0; q < 4; ++q) b[q] = brow[q * bq_stride + f4];
        ulonglong2 a[4];
        #pragma unroll
        for (int r = 0; r < 4; ++r) a[r] = *(const ulonglong2*)&arow[r * SSTR + f4 * 4];

        #pragma unroll
        for (int r = 0; r < 4; ++r)
            #pragma unroll
            for (int q = 0; q < 4; ++q) {
                acc[r][q] = f32x2_fma(a[r].x, b[q].x, acc[r][q]);
                acc[r][q] = f32x2_fma(a[r].y, b[q].y, acc[r][q]);
            }
    }

    // ---- write partial dots for 2 rows (peer group epilogues them) ----
    const int wr0 = g ? 0 : 2;                    // rows this warp WRITES
    #pragma unroll
    for (int rr = 0; rr < 2; ++rr) {
        int r = wr0 + rr;
        int row = p * 4 + r;
        #pragma unroll
        for (int q = 0; q < 4; ++q) {
            float lo, hi; f32x2_unpack(acc[r][q], lo, hi);
            pd[row * R_DIM + lane + 32 * q] = lo + hi;
        }
    }
    __syncthreads();

    // ---- epilogue for 2 rows (own partial + peer partial from pd) ----
    float nvq[4];
    #pragma unroll
    for (int q = 0; q < 4; ++q) nvq[q] = normv[lane + 32 * q];

    const int re0 = 2 - wr0;                      // rows this warp EPILOGUES
    float* outbase = out + ((size_t)n * R_DIM + i0 + p * 4) * R_DIM;

    #pragma unroll
    for (int rr = 0; rr < 2; ++rr) {
        int r = re0 + rr;
        int row = p * 4 + r;
        const float nu = normu[row];
        float ex[4];
        float s = 0.0f;
        #pragma unroll
        for (int q = 0; q < 4; ++q) {
            float lo, hi; f32x2_unpack(acc[r][q], lo, hi);
            float dot = (lo + hi) + pd[row * R_DIM + lane + 32 * q];
            float D = nu + nvq[q] - 2.0f * dot;
            float k = __expf(-D * inv2s2);        // in (0,1]
            ex[q] = __expf(k);                    // bounded arg, no max-sub
            s += ex[q];
        }
        #pragma unroll
        for (int o = 16; o > 0; o >>= 1)
            s += __shfl_xor_sync(0xffffffffu, s, o);
        const float inv = 1.0f / s;
        #pragma unroll
        for (int q = 0; q < 4; ++q)
            outbase[r * R_DIM + lane + 32 * q] = ex[q] * inv;
    }
}

extern "C" void kernel_launch(void* const* d_in, const int* in_sizes, int n_in,
                              void* d_out, int out_size) {
    const float4* x1    = (const float4*)d_in[0];
    const float4* x2    = (const float4*)d_in[1];
    const float*  sigma = (const float*)d_in[2];
    const float*  mean  = (const float*)d_in[3];
    float* out = (float*)d_out;

    const int smem_bytes = (R_DIM * SSTR + TIB * SSTR + TIB * R_DIM + TIB + R_DIM) * (int)sizeof(float);
    cudaFuncSetAttribute(gaussian_gram_splitf,
                         cudaFuncAttributeMaxDynamicSharedMemorySize, smem_bytes);

    dim3 grid(R_DIM / TIB, N_B);   // (4, 32) = 128 blocks -> 1 per SM
    dim3 block(512);
    gaussian_gram_splitf<<<grid, block, smem_bytes>>>(x1, x2, sigma, mean, out);
}